// round 9
// baseline (speedup 1.0000x reference)
#include <cuda_runtime.h>
#include <cuda_bf16.h>
#include <math.h>
#include <stdint.h>

#define SEQ       131072
#define NN        211
#define NC        10
#define NF        100
#define NPAIR     101          // column pairs: j0 = 10 + 2p, j1 = j0+1 (p=100 -> dummy j1)
#define NODES_PAD 212          // node 211 is a write-only dummy
#define TILE      256          // rows per CTA
#define THREADS   256
#define STRIDE    257          // odd -> conflict-free transpose writes AND row reads
#define MAXENT    224          // cnt <= 208 always (i < j0 <= 208)
#define NZW       7            // 211 bits -> 7 words of zero-mask per column

// Static device scratch (no allocations allowed)
__device__ float4   g_ent[NPAIR * MAXENT];   // (i*STRIDE as int bits, w0, w1, 0)
__device__ int      g_cnt[NPAIR];
__device__ float    g_cross[NPAIR];          // W[j0][j1]
__device__ int      g_act0[NPAIR];
__device__ int      g_act1[NPAIR];
__device__ unsigned g_zmask[NN * 8];         // bit i set iff i<j && W[i][j]==0
__device__ int      g_flag;

static __device__ __forceinline__ bool is_nan_bits(float v) {
    return (__float_as_uint(v) & 0x7fffffffu) > 0x7f800000u;
}
static __device__ __forceinline__ bool nonfinite(float v) {
    return (__float_as_uint(v) & 0x7f800000u) == 0x7f800000u;  // inf or NaN
}

static __device__ __forceinline__ float apply_act(int a, float z) {
    // 0: identity, 1: tanh, 2: relu (NaN-propagating), 3: sigmoid
    if (a == 0) return z;
    if (a == 1) return tanhf(z);
    if (a == 2) return (z < 0.0f) ? 0.0f : z;   // NaN -> NaN, matches jnp.maximum
    float e = expf(-z);
    return 1.0f / (1.0f + e);
}

// ---------------------------------------------------------------------------
// Kernel 0: build sparse pair lists + per-column zero-weight masks + reset flag
// One warp per column pair.
// ---------------------------------------------------------------------------
__global__ void build_lists(const float* __restrict__ W, const int* __restrict__ act_id) {
    int gwarp = (blockIdx.x * blockDim.x + threadIdx.x) >> 5;
    int lane  = threadIdx.x & 31;
    if (blockIdx.x == 0 && threadIdx.x == 0) g_flag = 0;
    if (gwarp >= NPAIR) return;

    int  j0   = NC + 2 * gwarp;
    int  j1   = j0 + 1;
    bool has1 = (j1 < NN);
    int  cnt  = 0;

    // fixed 7 iterations so every zero-mask word gets written
    for (int w = 0; w < NZW; w++) {
        int   base = w * 32;
        int   i    = base + lane;
        float w0 = 0.0f, w1 = 0.0f;
        if (i < j0)          w0 = W[i * NN + j0];
        if (i < j1 && has1)  w1 = W[i * NN + j1];   // includes i == j0 (cross)

        // sparse union list (parents strictly below j0; cross handled separately)
        bool nz = (i < j0) && ((w0 != 0.0f) || (w1 != 0.0f));
        unsigned m = __ballot_sync(0xffffffffu, nz);
        if (nz) {
            int pos = cnt + __popc(m & ((1u << lane) - 1u));
            g_ent[gwarp * MAXENT + pos] =
                make_float4(__int_as_float(i * STRIDE), w0, w1, 0.0f);
        }
        cnt += __popc(m);

        // zero-weight masks (ref dense-dot NaN genesis: v_i nonfinite * 0 = NaN)
        unsigned z0 = __ballot_sync(0xffffffffu, (i < j0) && (w0 == 0.0f));
        unsigned z1 = __ballot_sync(0xffffffffu, has1 && (i < j1) && (w1 == 0.0f));
        if (lane == 0) {
            g_zmask[j0 * 8 + w] = z0;
            if (has1) g_zmask[j1 * 8 + w] = z1;
        }
    }
    if (lane == 0) {
        g_cnt[gwarp]   = cnt;
        g_cross[gwarp] = has1 ? W[j0 * NN + j1] : 0.0f;
        g_act0[gwarp]  = act_id[j0];
        g_act1[gwarp]  = has1 ? act_id[j1] : 0;
    }
}

// ---------------------------------------------------------------------------
// Kernel 1: main rollout. One thread = one sequence row.
// ---------------------------------------------------------------------------
extern __shared__ float s_mem[];

__global__ __launch_bounds__(THREADS, 1)
void rollout(const float* __restrict__ causes,
             const float* __restrict__ noise,
             const int*   __restrict__ x_idx,
             const int*   __restrict__ y_idx,
             float*       __restrict__ out) {
    float*    buf = s_mem;                                    // NODES_PAD * STRIDE
    float4*   ent = (float4*)(s_mem + NODES_PAD * STRIDE);    // 2 * MAXENT
    unsigned* zm  = (unsigned*)(ent + 2 * MAXENT);            // NN * NZW

    const int tid  = threadIdx.x;
    const int warp = tid >> 5;
    const int lane = tid & 31;
    const long row0 = (long)blockIdx.x * TILE;

    // ---- prefill: buf[j][r] = noise[row0+r][j] (transposed), causes for j<NC
    for (int r = warp; r < TILE; r += 8) {
        const float* nrow = noise + (row0 + r) * NN;
        for (int c = lane; c < NN; c += 32)
            buf[c * STRIDE + r] = nrow[c];
    }
    for (int r = warp; r < TILE; r += 8) {
        if (lane < NC)
            buf[lane * STRIDE + r] = causes[(row0 + r) * NC + lane];
    }
    buf[211 * STRIDE + tid] = 0.0f;   // dummy column

    // stage zero-masks into shared (compact NZW words per column)
    for (int i = tid; i < NN * NZW; i += THREADS)
        zm[i] = g_zmask[(i / NZW) * 8 + (i % NZW)];

    // stage pair 0 into buffer 0
    if (tid < g_cnt[0]) ent[tid] = g_ent[tid];
    __syncthreads();

    // per-row nonfinite bitmask
    unsigned m0_=0,m1_=0,m2_=0,m3_=0,m4_=0,m5_=0,m6_=0;
    bool has_nf = false;
    const float QNAN = __int_as_float(0x7fc00000);

    int cur = 0;
    for (int p = 0; p < NPAIR; p++) {
        const int cnt = g_cnt[p];

        // prefetch next pair's list into registers
        float4 pre = make_float4(0.f, 0.f, 0.f, 0.f);
        int cntn = 0;
        if (p + 1 < NPAIR) {
            cntn = g_cnt[p + 1];
            if (tid < cntn) pre = g_ent[(p + 1) * MAXENT + tid];
        }

        const float4* E = ent + cur * MAXENT;
        const int j0 = NC + 2 * p;
        const int j1 = j0 + 1;            // p=100 -> 211 (dummy)

        float z0 = buf[j0 * STRIDE + tid];    // noise prefill
        float z1 = buf[j1 * STRIDE + tid];
        float a0 = 0.f, a1 = 0.f, b0 = 0.f, b1 = 0.f;

        int k = 0;
        #pragma unroll 4
        for (; k + 2 <= cnt; k += 2) {
            float4 e0 = E[k];
            float4 e1 = E[k + 1];
            float  v0 = buf[__float_as_int(e0.x) + tid];
            float  v1 = buf[__float_as_int(e1.x) + tid];
            a0 = fmaf(v0, e0.y, a0);
            a1 = fmaf(v0, e0.z, a1);
            b0 = fmaf(v1, e1.y, b0);
            b1 = fmaf(v1, e1.z, b1);
        }
        if (k < cnt) {
            float4 e0 = E[k];
            float  v0 = buf[__float_as_int(e0.x) + tid];
            a0 = fmaf(v0, e0.y, a0);
            a1 = fmaf(v0, e0.z, a1);
        }
        z0 += a0 + b0;
        z1 += a1 + b1;

        // --- ref dense-dot NaN genesis: zero-weight x nonfinite parent -> NaN
        // (warp-uniform ballots, executed unconditionally by all 32 lanes)
        const bool wnf0 = __ballot_sync(0xffffffffu, has_nf) != 0u;
        if (wnf0) {
            const unsigned* z0m = zm + j0 * NZW;
            unsigned h0 = (m0_&z0m[0])|(m1_&z0m[1])|(m2_&z0m[2])|(m3_&z0m[3])
                        |(m4_&z0m[4])|(m5_&z0m[5])|(m6_&z0m[6]);
            if (h0) z0 = QNAN;
        }

        float v0 = apply_act(g_act0[p], z0);
        if (nonfinite(v0)) {
            has_nf = true;
            unsigned bit = 1u << (j0 & 31);
            switch (j0 >> 5) {
                case 0: m0_|=bit; break; case 1: m1_|=bit; break;
                case 2: m2_|=bit; break; case 3: m3_|=bit; break;
                case 4: m4_|=bit; break; case 5: m5_|=bit; break;
                default: m6_|=bit; break;
            }
        }

        z1 = fmaf(v0, g_cross[p], z1);

        // uniform re-ballot AFTER v0 update (also catches same-pair overflow)
        const bool wnf1 = __ballot_sync(0xffffffffu, has_nf) != 0u;
        if (wnf1 && j1 < NN) {
            const unsigned* z1m = zm + j1 * NZW;
            unsigned h1 = (m0_&z1m[0])|(m1_&z1m[1])|(m2_&z1m[2])|(m3_&z1m[3])
                        |(m4_&z1m[4])|(m5_&z1m[5])|(m6_&z1m[6]);
            if (h1) z1 = QNAN;
        }

        float v1 = apply_act(g_act1[p], z1);
        if (j1 < NN && nonfinite(v1)) {
            has_nf = true;
            unsigned bit = 1u << (j1 & 31);
            switch (j1 >> 5) {
                case 0: m0_|=bit; break; case 1: m1_|=bit; break;
                case 2: m2_|=bit; break; case 3: m3_|=bit; break;
                case 4: m4_|=bit; break; case 5: m5_|=bit; break;
                default: m6_|=bit; break;
            }
        }

        buf[j0 * STRIDE + tid] = v0;     // thread-private columns: no sync needed
        buf[j1 * STRIDE + tid] = v1;

        if (tid < cntn) ent[(cur ^ 1) * MAXENT + tid] = pre;
        __syncthreads();                 // staged list visible before next pair
        cur ^= 1;
    }

    // ---- output gather. Reuse ent space for premultiplied x indices.
    int* xi = (int*)ent;
    if (tid < NF) xi[tid] = x_idx[tid] * STRIDE;
    __syncthreads();

    const int yoff = y_idx[0] * STRIDE;
    bool bad = false;

    for (int r = warp; r < TILE; r += 8) {
        const long obase = (row0 + r) * NF;
        for (int f = lane; f < NF; f += 32) {
            float v = buf[xi[f] + r];
            bad |= is_nan_bits(v);
            out[obase + f] = v;
        }
    }
    {
        float yv = buf[yoff + tid];
        bad |= is_nan_bits(yv);
        out[(long)SEQ * NF + row0 + tid] = yv;
    }
    if (__any_sync(0xffffffffu, bad)) {
        if (lane == 0) atomicOr(&g_flag, 1);
    }
}

// ---------------------------------------------------------------------------
// Kernel 2: NaN fallback (X -> 0, y -> -100). Early-exits when clean.
// ---------------------------------------------------------------------------
__global__ void fixup(float* __restrict__ out) {
    if (g_flag == 0) return;
    const long nx     = (long)SEQ * NF;
    const long stride = (long)gridDim.x * blockDim.x;
    const long t0     = (long)blockIdx.x * blockDim.x + threadIdx.x;
    for (long i = t0; i < nx; i += stride)
        out[i] = 0.0f;
    for (long j = t0; j < SEQ; j += stride)
        out[nx + j] = -100.0f;
}

// ---------------------------------------------------------------------------
extern "C" void kernel_launch(void* const* d_in, const int* in_sizes, int n_in,
                              void* d_out, int out_size) {
    const float* causes = (const float*)d_in[0];
    const float* noise  = (const float*)d_in[1];
    const float* W      = (const float*)d_in[2];
    const int*   act_id = (const int*)d_in[3];
    const int*   x_idx  = (const int*)d_in[4];
    const int*   y_idx  = (const int*)d_in[5];
    float*       out    = (float*)d_out;

    const int smem_bytes = (NODES_PAD * STRIDE) * 4      // buf
                         + 2 * MAXENT * 16               // ent double buffer
                         + NN * NZW * 4;                 // zero masks

    // Unconditional (no static guard — harness rules). Idempotent, cheap,
    // and not a stream op, so it is graph-capture safe.
    cudaFuncSetAttribute(rollout, cudaFuncAttributeMaxDynamicSharedMemorySize,
                         smem_bytes);

    build_lists<<<(NPAIR * 32 + 255) / 256, 256>>>(W, act_id);
    rollout<<<SEQ / TILE, THREADS, smem_bytes>>>(causes, noise, x_idx, y_idx, out);
    fixup<<<512, 256>>>(out);
}

// round 10
// speedup vs baseline: 1.0312x; 1.0312x over previous
#include <cuda_runtime.h>
#include <cuda_bf16.h>
#include <math.h>
#include <stdint.h>

#define SEQ       131072
#define NN        211
#define NC        10
#define NF        100
#define NPAIR     101          // column pairs: j0 = 10 + 2p, j1 = j0+1 (p=100 -> dummy j1)
#define NODES_PAD 212          // node 211 is a write-only dummy
#define TILE      256          // rows per CTA
#define THREADS   256
#define STRIDE    257          // odd -> conflict-free transpose writes AND row reads
#define MAXENT    224          // cnt <= 208 always (i < j0 <= 208)
#define NZW       7            // 211 bits -> 7 words of zero-mask per column

// Static device scratch (no allocations allowed)
__device__ float4   g_ent[NPAIR * MAXENT];   // (i*STRIDE as int bits, w0, w1, 0)
__device__ int      g_cnt[NPAIR];
__device__ float    g_cross[NPAIR];          // W[j0][j1]
__device__ int      g_act0[NPAIR];
__device__ int      g_act1[NPAIR];
__device__ unsigned g_zmask[NN * 8];         // bit i set iff i<j && W[i][j]==0
__device__ int      g_flag;

static __device__ __forceinline__ bool is_nan_bits(float v) {
    return (__float_as_uint(v) & 0x7fffffffu) > 0x7f800000u;
}
static __device__ __forceinline__ bool nonfinite(float v) {
    return (__float_as_uint(v) & 0x7f800000u) == 0x7f800000u;  // inf or NaN
}

static __device__ __forceinline__ float apply_act(int a, float z) {
    // 0: identity, 1: tanh, 2: relu (NaN-propagating), 3: sigmoid
    if (a == 0) return z;
    if (a == 1) return tanhf(z);
    if (a == 2) return (z < 0.0f) ? 0.0f : z;   // NaN -> NaN, matches jnp.maximum
    float e = expf(-z);
    return 1.0f / (1.0f + e);
}

// ---------------------------------------------------------------------------
// Kernel 0: build sparse pair lists + per-column zero-weight masks + reset flag
// One warp per column pair.
// ---------------------------------------------------------------------------
__global__ void build_lists(const float* __restrict__ W, const int* __restrict__ act_id) {
    int gwarp = (blockIdx.x * blockDim.x + threadIdx.x) >> 5;
    int lane  = threadIdx.x & 31;
    if (blockIdx.x == 0 && threadIdx.x == 0) g_flag = 0;
    if (gwarp >= NPAIR) return;

    int  j0   = NC + 2 * gwarp;
    int  j1   = j0 + 1;
    bool has1 = (j1 < NN);
    int  cnt  = 0;

    // fixed 7 iterations so every zero-mask word gets written
    for (int w = 0; w < NZW; w++) {
        int   base = w * 32;
        int   i    = base + lane;
        float w0 = 0.0f, w1 = 0.0f;
        if (i < j0)          w0 = W[i * NN + j0];
        if (i < j1 && has1)  w1 = W[i * NN + j1];   // includes i == j0 (cross)

        // sparse union list (parents strictly below j0; cross handled separately)
        bool nz = (i < j0) && ((w0 != 0.0f) || (w1 != 0.0f));
        unsigned m = __ballot_sync(0xffffffffu, nz);
        if (nz) {
            int pos = cnt + __popc(m & ((1u << lane) - 1u));
            g_ent[gwarp * MAXENT + pos] =
                make_float4(__int_as_float(i * STRIDE), w0, w1, 0.0f);
        }
        cnt += __popc(m);

        // zero-weight masks (ref dense-dot NaN genesis: v_i nonfinite * 0 = NaN)
        unsigned z0 = __ballot_sync(0xffffffffu, (i < j0) && (w0 == 0.0f));
        unsigned z1 = __ballot_sync(0xffffffffu, has1 && (i < j1) && (w1 == 0.0f));
        if (lane == 0) {
            g_zmask[j0 * 8 + w] = z0;
            if (has1) g_zmask[j1 * 8 + w] = z1;
        }
    }
    if (lane == 0) {
        g_cnt[gwarp]   = cnt;
        g_cross[gwarp] = has1 ? W[j0 * NN + j1] : 0.0f;
        g_act0[gwarp]  = act_id[j0];
        g_act1[gwarp]  = has1 ? act_id[j1] : 0;
    }
}

// ---------------------------------------------------------------------------
// Kernel 1: main rollout. One thread = one sequence row.
// ---------------------------------------------------------------------------
extern __shared__ float s_mem[];

__global__ __launch_bounds__(THREADS, 1)
void rollout(const float* __restrict__ causes,
             const float* __restrict__ noise,
             const int*   __restrict__ x_idx,
             const int*   __restrict__ y_idx,
             float*       __restrict__ out) {
    float*    buf     = s_mem;                                  // NODES_PAD * STRIDE
    float4*   ent     = (float4*)(s_mem + NODES_PAD * STRIDE);  // 2 * MAXENT
    unsigned* zm      = (unsigned*)(ent + 2 * MAXENT);          // NN * NZW
    int*      s_cnt   = (int*)(zm + NN * NZW);                  // NPAIR
    int*      s_act   = s_cnt + NPAIR;                          // NPAIR (act0 | act1<<8)
    float*    s_cross = (float*)(s_act + NPAIR);                // NPAIR

    const int tid  = threadIdx.x;
    const int warp = tid >> 5;
    const int lane = tid & 31;
    const long row0 = (long)blockIdx.x * TILE;

    // ---- control preload: per-pair metadata into shared (hides per-pair LDGs)
    if (tid < NPAIR) {
        s_cnt[tid]   = g_cnt[tid];
        s_act[tid]   = g_act0[tid] | (g_act1[tid] << 8);
        s_cross[tid] = g_cross[tid];
    }

    // ---- prefill: buf[j][r] = noise[row0+r][j] (transposed), causes for j<NC
    for (int r = warp; r < TILE; r += 8) {
        const float* nrow = noise + (row0 + r) * NN;
        for (int c = lane; c < NN; c += 32)
            buf[c * STRIDE + r] = nrow[c];
    }
    for (int r = warp; r < TILE; r += 8) {
        if (lane < NC)
            buf[lane * STRIDE + r] = causes[(row0 + r) * NC + lane];
    }
    buf[211 * STRIDE + tid] = 0.0f;   // dummy column

    // stage zero-masks into shared (compact NZW words per column)
    for (int i = tid; i < NN * NZW; i += THREADS)
        zm[i] = g_zmask[(i / NZW) * 8 + (i % NZW)];

    // stage pair 0 into buffer 0 (count direct from global this once)
    if (tid < g_cnt[0]) ent[tid] = g_ent[tid];
    __syncthreads();

    // per-row nonfinite bitmask
    unsigned m0_=0,m1_=0,m2_=0,m3_=0,m4_=0,m5_=0,m6_=0;
    bool has_nf = false;
    const float QNAN = __int_as_float(0x7fc00000);

    int cur = 0;
    for (int p = 0; p < NPAIR; p++) {
        const int cnt = s_cnt[p];          // LDS broadcast (cheap)

        // prefetch next pair's list into registers (LDG hidden under compute)
        float4 pre = make_float4(0.f, 0.f, 0.f, 0.f);
        int cntn = 0;
        if (p + 1 < NPAIR) {
            cntn = s_cnt[p + 1];
            if (tid < cntn) pre = g_ent[(p + 1) * MAXENT + tid];
        }

        const float4* E = ent + cur * MAXENT;
        const int j0 = NC + 2 * p;
        const int j1 = j0 + 1;             // p=100 -> 211 (dummy)
        const int actw  = s_act[p];
        const float crs = s_cross[p];

        float z0 = buf[j0 * STRIDE + tid];   // noise prefill
        float z1 = buf[j1 * STRIDE + tid];
        float a0 = 0.f, a1 = 0.f, b0 = 0.f, b1 = 0.f;

        // ---- branch-free batched mainloop: 8 entries per straight-line block.
        // Entry LDS (broadcast) batched first, then 8 independent value LDS
        // (MLP=8), then FMAs into two alternating accumulator pairs.
        const int kend = cnt & ~7;
        int k = 0;
        for (; k < kend; k += 8) {
            float4 e[8];
            #pragma unroll
            for (int u = 0; u < 8; u++) e[u] = E[k + u];
            float v[8];
            #pragma unroll
            for (int u = 0; u < 8; u++) v[u] = buf[__float_as_int(e[u].x) + tid];
            #pragma unroll
            for (int u = 0; u < 8; u += 2) {
                a0 = fmaf(v[u],   e[u].y,   a0);
                a1 = fmaf(v[u],   e[u].z,   a1);
                b0 = fmaf(v[u+1], e[u+1].y, b0);
                b1 = fmaf(v[u+1], e[u+1].z, b1);
            }
        }
        for (; k < cnt; k++) {             // <= 7 remainder entries
            float4 e0 = E[k];
            float  v0 = buf[__float_as_int(e0.x) + tid];
            a0 = fmaf(v0, e0.y, a0);
            a1 = fmaf(v0, e0.z, a1);
        }
        z0 += a0 + b0;
        z1 += a1 + b1;

        // --- ref dense-dot NaN genesis: zero-weight x nonfinite parent -> NaN
        // (warp-uniform ballots, executed unconditionally by all 32 lanes)
        const bool wnf0 = __ballot_sync(0xffffffffu, has_nf) != 0u;
        if (wnf0) {
            const unsigned* z0m = zm + j0 * NZW;
            unsigned h0 = (m0_&z0m[0])|(m1_&z0m[1])|(m2_&z0m[2])|(m3_&z0m[3])
                        |(m4_&z0m[4])|(m5_&z0m[5])|(m6_&z0m[6]);
            if (h0) z0 = QNAN;
        }

        float v0 = apply_act(actw & 0xff, z0);
        if (nonfinite(v0)) {
            has_nf = true;
            unsigned bit = 1u << (j0 & 31);
            switch (j0 >> 5) {
                case 0: m0_|=bit; break; case 1: m1_|=bit; break;
                case 2: m2_|=bit; break; case 3: m3_|=bit; break;
                case 4: m4_|=bit; break; case 5: m5_|=bit; break;
                default: m6_|=bit; break;
            }
        }

        z1 = fmaf(v0, crs, z1);

        // uniform re-ballot AFTER v0 update (also catches same-pair overflow)
        const bool wnf1 = __ballot_sync(0xffffffffu, has_nf) != 0u;
        if (wnf1 && j1 < NN) {
            const unsigned* z1m = zm + j1 * NZW;
            unsigned h1 = (m0_&z1m[0])|(m1_&z1m[1])|(m2_&z1m[2])|(m3_&z1m[3])
                        |(m4_&z1m[4])|(m5_&z1m[5])|(m6_&z1m[6]);
            if (h1) z1 = QNAN;
        }

        float v1 = apply_act((actw >> 8) & 0xff, z1);
        if (j1 < NN && nonfinite(v1)) {
            has_nf = true;
            unsigned bit = 1u << (j1 & 31);
            switch (j1 >> 5) {
                case 0: m0_|=bit; break; case 1: m1_|=bit; break;
                case 2: m2_|=bit; break; case 3: m3_|=bit; break;
                case 4: m4_|=bit; break; case 5: m5_|=bit; break;
                default: m6_|=bit; break;
            }
        }

        buf[j0 * STRIDE + tid] = v0;     // thread-private columns: no sync needed
        buf[j1 * STRIDE + tid] = v1;

        if (tid < cntn) ent[(cur ^ 1) * MAXENT + tid] = pre;
        __syncthreads();                 // staged list visible before next pair
        cur ^= 1;
    }

    // ---- output gather. Reuse ent space for premultiplied x indices.
    int* xi = (int*)ent;
    if (tid < NF) xi[tid] = x_idx[tid] * STRIDE;
    __syncthreads();

    const int yoff = y_idx[0] * STRIDE;
    bool bad = false;

    for (int r = warp; r < TILE; r += 8) {
        const long obase = (row0 + r) * NF;
        for (int f = lane; f < NF; f += 32) {
            float v = buf[xi[f] + r];
            bad |= is_nan_bits(v);
            out[obase + f] = v;
        }
    }
    {
        float yv = buf[yoff + tid];
        bad |= is_nan_bits(yv);
        out[(long)SEQ * NF + row0 + tid] = yv;
    }
    if (__any_sync(0xffffffffu, bad)) {
        if (lane == 0) atomicOr(&g_flag, 1);
    }
}

// ---------------------------------------------------------------------------
// Kernel 2: NaN fallback (X -> 0, y -> -100). Early-exits when clean.
// ---------------------------------------------------------------------------
__global__ void fixup(float* __restrict__ out) {
    if (g_flag == 0) return;
    const long nx     = (long)SEQ * NF;
    const long stride = (long)gridDim.x * blockDim.x;
    const long t0     = (long)blockIdx.x * blockDim.x + threadIdx.x;
    for (long i = t0; i < nx; i += stride)
        out[i] = 0.0f;
    for (long j = t0; j < SEQ; j += stride)
        out[nx + j] = -100.0f;
}

// ---------------------------------------------------------------------------
extern "C" void kernel_launch(void* const* d_in, const int* in_sizes, int n_in,
                              void* d_out, int out_size) {
    const float* causes = (const float*)d_in[0];
    const float* noise  = (const float*)d_in[1];
    const float* W      = (const float*)d_in[2];
    const int*   act_id = (const int*)d_in[3];
    const int*   x_idx  = (const int*)d_in[4];
    const int*   y_idx  = (const int*)d_in[5];
    float*       out    = (float*)d_out;

    const int smem_bytes = (NODES_PAD * STRIDE) * 4      // buf        217,936
                         + 2 * MAXENT * 16               // ent        + 7,168
                         + NN * NZW * 4                  // zero masks + 5,908
                         + NPAIR * 12;                   // ctrl       + 1,212
                                                         // = 232,224 <= 232,448

    // Unconditional (no static guard — harness rules). Idempotent, cheap,
    // and not a stream op, so it is graph-capture safe.
    cudaFuncSetAttribute(rollout, cudaFuncAttributeMaxDynamicSharedMemorySize,
                         smem_bytes);

    build_lists<<<(NPAIR * 32 + 255) / 256, 256>>>(W, act_id);
    rollout<<<SEQ / TILE, THREADS, smem_bytes>>>(causes, noise, x_idx, y_idx, out);
    fixup<<<512, 256>>>(out);
}

// round 13
// speedup vs baseline: 1.0941x; 1.0610x over previous
#include <cuda_runtime.h>
#include <cuda_bf16.h>
#include <math.h>
#include <stdint.h>

#define SEQ       131072
#define NN        211
#define NC        10
#define NF        100
#define NPAIR     101          // column pairs: j0 = 10 + 2p, j1 = j0+1 (p=100 -> dummy j1)
#define NODES_PAD 212          // node 211 is a write-only dummy
#define TILE      256          // rows per CTA
#define THREADS   512          // 2 threads per row
#define STRIDE    257          // odd -> conflict-free transpose writes AND row reads
#define MAXENT    224          // cnt <= 208 always (i < j0 <= 208)
#define NZW       7            // 211 bits -> 7 words of zero-mask per column

// Static device scratch (no allocations allowed)
__device__ float4   g_ent[NPAIR * MAXENT];   // (i*STRIDE as int bits, w0, w1, 0)
__device__ int      g_cnt[NPAIR];
__device__ float    g_cross[NPAIR];          // W[j0][j1]
__device__ int      g_act0[NPAIR];
__device__ int      g_act1[NPAIR];
__device__ unsigned g_zmask[NN * 8];         // bit i set iff i<j && W[i][j]==0
__device__ int      g_flag;

static __device__ __forceinline__ bool is_nan_bits(float v) {
    return (__float_as_uint(v) & 0x7fffffffu) > 0x7f800000u;
}
static __device__ __forceinline__ bool nonfinite(float v) {
    return (__float_as_uint(v) & 0x7f800000u) == 0x7f800000u;  // inf or NaN
}

static __device__ __forceinline__ float apply_act(int a, float z) {
    // 0: identity, 1: tanh, 2: relu (NaN-propagating), 3: sigmoid
    if (a == 0) return z;
    if (a == 1) return tanhf(z);
    if (a == 2) return (z < 0.0f) ? 0.0f : z;   // NaN -> NaN, matches jnp.maximum
    float e = expf(-z);
    return 1.0f / (1.0f + e);
}

// ---------------------------------------------------------------------------
// Kernel 0: build sparse pair lists + per-column zero-weight masks + reset flag
// One warp per column pair.
// ---------------------------------------------------------------------------
__global__ void build_lists(const float* __restrict__ W, const int* __restrict__ act_id) {
    int gwarp = (blockIdx.x * blockDim.x + threadIdx.x) >> 5;
    int lane  = threadIdx.x & 31;
    if (blockIdx.x == 0 && threadIdx.x == 0) g_flag = 0;
    if (gwarp >= NPAIR) return;

    int  j0   = NC + 2 * gwarp;
    int  j1   = j0 + 1;
    bool has1 = (j1 < NN);
    int  cnt  = 0;

    for (int w = 0; w < NZW; w++) {
        int   i  = w * 32 + lane;
        float w0 = 0.0f, w1 = 0.0f;
        if (i < j0)          w0 = W[i * NN + j0];
        if (i < j1 && has1)  w1 = W[i * NN + j1];   // includes i == j0 (cross)

        bool nz = (i < j0) && ((w0 != 0.0f) || (w1 != 0.0f));
        unsigned m = __ballot_sync(0xffffffffu, nz);
        if (nz) {
            int pos = cnt + __popc(m & ((1u << lane) - 1u));
            g_ent[gwarp * MAXENT + pos] =
                make_float4(__int_as_float(i * STRIDE), w0, w1, 0.0f);
        }
        cnt += __popc(m);

        unsigned z0 = __ballot_sync(0xffffffffu, (i < j0) && (w0 == 0.0f));
        unsigned z1 = __ballot_sync(0xffffffffu, has1 && (i < j1) && (w1 == 0.0f));
        if (lane == 0) {
            g_zmask[j0 * 8 + w] = z0;
            if (has1) g_zmask[j1 * 8 + w] = z1;
        }
    }
    if (lane == 0) {
        g_cnt[gwarp]   = cnt;
        g_cross[gwarp] = has1 ? W[j0 * NN + j1] : 0.0f;
        g_act0[gwarp]  = act_id[j0];
        g_act1[gwarp]  = has1 ? act_id[j1] : 0;
    }
}

// ---------------------------------------------------------------------------
// Kernel 1: main rollout. TWO threads per sequence row (entry halves split by
// parity, combined with shfl_xor over lane pairs). 16 warps/CTA -> 4/SMSP.
// ---------------------------------------------------------------------------
extern __shared__ float s_mem[];

__global__ __launch_bounds__(THREADS, 1)
void rollout(const float* __restrict__ causes,
             const float* __restrict__ noise,
             const int*   __restrict__ x_idx,
             const int*   __restrict__ y_idx,
             float*       __restrict__ out) {
    float*    buf     = s_mem;                                  // NODES_PAD * STRIDE
    float4*   ent     = (float4*)(s_mem + NODES_PAD * STRIDE);  // 2 * MAXENT
    unsigned* zm      = (unsigned*)(ent + 2 * MAXENT);          // NN * NZW
    int*      s_cnt   = (int*)(zm + NN * NZW);                  // NPAIR
    int*      s_act   = s_cnt + NPAIR;                          // NPAIR (act0 | act1<<8)
    float*    s_cross = (float*)(s_act + NPAIR);                // NPAIR

    const int tid  = threadIdx.x;
    const int warp = tid >> 5;
    const int lane = tid & 31;
    const int row  = tid >> 1;            // 0..255
    const int h    = tid & 1;             // entry-parity half
    const long row0 = (long)blockIdx.x * TILE;

    // ---- control preload
    if (tid < NPAIR) {
        s_cnt[tid]   = g_cnt[tid];
        s_act[tid]   = g_act0[tid] | (g_act1[tid] << 8);
        s_cross[tid] = g_cross[tid];
    }

    // ---- prefill: buf[j][r] = noise[row0+r][j] (transposed), causes for j<NC
    for (int r = warp; r < TILE; r += 16) {
        const float* nrow = noise + (row0 + r) * NN;
        for (int c = lane; c < NN; c += 32)
            buf[c * STRIDE + r] = nrow[c];
    }
    for (int r = warp; r < TILE; r += 16) {
        if (lane < NC)
            buf[lane * STRIDE + r] = causes[(row0 + r) * NC + lane];
    }
    if (tid < TILE) buf[211 * STRIDE + tid] = 0.0f;   // dummy column

    // stage zero-masks into shared (compact NZW words per column)
    for (int i = tid; i < NN * NZW; i += THREADS)
        zm[i] = g_zmask[(i / NZW) * 8 + (i % NZW)];

    // stage pair 0 into buffer 0
    if (tid < g_cnt[0]) ent[tid] = g_ent[tid];
    __syncthreads();

    // per-row nonfinite bitmask (identical on both lane-halves of a row)
    unsigned m0_=0,m1_=0,m2_=0,m3_=0,m4_=0,m5_=0,m6_=0;
    bool has_nf = false;
    const float QNAN = __int_as_float(0x7fc00000);

    int cur = 0;
    for (int p = 0; p < NPAIR; p++) {
        const int cnt = s_cnt[p];

        // prefetch next pair's list into registers
        float4 pre = make_float4(0.f, 0.f, 0.f, 0.f);
        int cntn = 0;
        if (p + 1 < NPAIR) {
            cntn = s_cnt[p + 1];
            if (tid < cntn) pre = g_ent[(p + 1) * MAXENT + tid];
        }

        const float4* E = ent + cur * MAXENT;
        const int j0 = NC + 2 * p;
        const int j1 = j0 + 1;             // p=100 -> 211 (dummy)
        const int actw  = s_act[p];
        const float crs = s_cross[p];

        float z0 = buf[j0 * STRIDE + row];   // same value on both halves
        float z1 = buf[j1 * STRIDE + row];
        float a0 = 0.f, a1 = 0.f;

        // ---- this thread's half: entries k = h, h+2, h+4, ...
        // batch of 4 entries per straight-line block (stride-2 within batch)
        int k = h;
        for (; k + 6 < cnt; k += 8) {
            float4 e0 = E[k];
            float4 e1 = E[k + 2];
            float4 e2 = E[k + 4];
            float4 e3 = E[k + 6];
            float  v0 = buf[__float_as_int(e0.x) + row];
            float  v1 = buf[__float_as_int(e1.x) + row];
            float  v2 = buf[__float_as_int(e2.x) + row];
            float  v3 = buf[__float_as_int(e3.x) + row];
            a0 = fmaf(v0, e0.y, a0);
            a1 = fmaf(v0, e0.z, a1);
            a0 = fmaf(v1, e1.y, a0);
            a1 = fmaf(v1, e1.z, a1);
            a0 = fmaf(v2, e2.y, a0);
            a1 = fmaf(v2, e2.z, a1);
            a0 = fmaf(v3, e3.y, a0);
            a1 = fmaf(v3, e3.z, a1);
        }
        for (; k < cnt; k += 2) {
            float4 e0 = E[k];
            float  v0 = buf[__float_as_int(e0.x) + row];
            a0 = fmaf(v0, e0.y, a0);
            a1 = fmaf(v0, e0.z, a1);
        }

        // combine the two halves (lane pairs are adjacent lanes in one warp)
        a0 += __shfl_xor_sync(0xffffffffu, a0, 1);
        a1 += __shfl_xor_sync(0xffffffffu, a1, 1);
        z0 += a0;
        z1 += a1;

        // --- ref dense-dot NaN genesis: zero-weight x nonfinite parent -> NaN
        const bool wnf0 = __ballot_sync(0xffffffffu, has_nf) != 0u;
        if (wnf0) {
            const unsigned* z0m = zm + j0 * NZW;
            unsigned h0 = (m0_&z0m[0])|(m1_&z0m[1])|(m2_&z0m[2])|(m3_&z0m[3])
                        |(m4_&z0m[4])|(m5_&z0m[5])|(m6_&z0m[6]);
            if (h0) z0 = QNAN;
        }

        float v0 = apply_act(actw & 0xff, z0);   // computed identically on both halves
        if (nonfinite(v0)) {
            has_nf = true;
            unsigned bit = 1u << (j0 & 31);
            switch (j0 >> 5) {
                case 0: m0_|=bit; break; case 1: m1_|=bit; break;
                case 2: m2_|=bit; break; case 3: m3_|=bit; break;
                case 4: m4_|=bit; break; case 5: m5_|=bit; break;
                default: m6_|=bit; break;
            }
        }

        z1 = fmaf(v0, crs, z1);

        const bool wnf1 = __ballot_sync(0xffffffffu, has_nf) != 0u;
        if (wnf1 && j1 < NN) {
            const unsigned* z1m = zm + j1 * NZW;
            unsigned h1 = (m0_&z1m[0])|(m1_&z1m[1])|(m2_&z1m[2])|(m3_&z1m[3])
                        |(m4_&z1m[4])|(m5_&z1m[5])|(m6_&z1m[6]);
            if (h1) z1 = QNAN;
        }

        float v1 = apply_act((actw >> 8) & 0xff, z1);
        if (j1 < NN && nonfinite(v1)) {
            has_nf = true;
            unsigned bit = 1u << (j1 & 31);
            switch (j1 >> 5) {
                case 0: m0_|=bit; break; case 1: m1_|=bit; break;
                case 2: m2_|=bit; break; case 3: m3_|=bit; break;
                case 4: m4_|=bit; break; case 5: m5_|=bit; break;
                default: m6_|=bit; break;
            }
        }

        // both halves store the same value (benign same-value race)
        buf[j0 * STRIDE + row] = v0;
        buf[j1 * STRIDE + row] = v1;

        if (tid < cntn) ent[(cur ^ 1) * MAXENT + tid] = pre;
        __syncthreads();                 // staged list visible before next pair
        cur ^= 1;
    }

    // ---- output gather. Reuse ent space for premultiplied x indices.
    int* xi = (int*)ent;
    if (tid < NF) xi[tid] = x_idx[tid] * STRIDE;
    __syncthreads();

    const int yoff = y_idx[0] * STRIDE;
    bool bad = false;

    for (int r = warp; r < TILE; r += 16) {
        const long obase = (row0 + r) * NF;
        for (int f = lane; f < NF; f += 32) {
            float v = buf[xi[f] + r];
            bad |= is_nan_bits(v);
            out[obase + f] = v;
        }
    }
    if (tid < TILE) {
        float yv = buf[yoff + tid];
        bad |= is_nan_bits(yv);
        out[(long)SEQ * NF + row0 + tid] = yv;
    }
    if (__any_sync(0xffffffffu, bad)) {
        if (lane == 0) atomicOr(&g_flag, 1);
    }
}

// ---------------------------------------------------------------------------
// Kernel 2: NaN fallback (X -> 0, y -> -100). Early-exits when clean.
// ---------------------------------------------------------------------------
__global__ void fixup(float* __restrict__ out) {
    if (g_flag == 0) return;
    const long nx     = (long)SEQ * NF;
    const long stride = (long)gridDim.x * blockDim.x;
    const long t0     = (long)blockIdx.x * blockDim.x + threadIdx.x;
    for (long i = t0; i < nx; i += stride)
        out[i] = 0.0f;
    for (long j = t0; j < SEQ; j += stride)
        out[nx + j] = -100.0f;
}

// ---------------------------------------------------------------------------
extern "C" void kernel_launch(void* const* d_in, const int* in_sizes, int n_in,
                              void* d_out, int out_size) {
    const float* causes = (const float*)d_in[0];
    const float* noise  = (const float*)d_in[1];
    const float* W      = (const float*)d_in[2];
    const int*   act_id = (const int*)d_in[3];
    const int*   x_idx  = (const int*)d_in[4];
    const int*   y_idx  = (const int*)d_in[5];
    float*       out    = (float*)d_out;

    const int smem_bytes = (NODES_PAD * STRIDE) * 4      // buf        217,936
                         + 2 * MAXENT * 16               // ent        + 7,168
                         + NN * NZW * 4                  // zero masks + 5,908
                         + NPAIR * 12;                   // ctrl       + 1,212
                                                         // = 232,224 <= 232,448

    cudaFuncSetAttribute(rollout, cudaFuncAttributeMaxDynamicSharedMemorySize,
                         smem_bytes);

    build_lists<<<(NPAIR * 32 + 255) / 256, 256>>>(W, act_id);
    rollout<<<SEQ / TILE, THREADS, smem_bytes>>>(causes, noise, x_idx, y_idx, out);
    fixup<<<512, 256>>>(out);
}